// round 2
// baseline (speedup 1.0000x reference)
#include <cuda_runtime.h>
#include <math.h>

#define B_   8
#define CIN  128
#define CK   64
#define CV   64
#define CO   128
#define N_   4096
#define KVCHUNKS 16

typedef unsigned long long u64;

// ---------------- f32x2 packed-FMA helpers ----------------
__device__ __forceinline__ void fma2(u64 &d, u64 a, u64 b) {
    asm("fma.rn.f32x2 %0, %1, %2, %0;" : "+l"(d) : "l"(a), "l"(b));
}
__device__ __forceinline__ u64 bcast2(float x) {
    u64 r; asm("mov.b64 %0, {%1, %1};" : "=l"(r) : "f"(x)); return r;
}
__device__ __forceinline__ u64 pack2(float lo, float hi) {
    u64 r; asm("mov.b64 %0, {%1, %2};" : "=l"(r) : "f"(lo), "f"(hi)); return r;
}
__device__ __forceinline__ void unpack2(float &lo, float &hi, u64 v) {
    asm("mov.b64 {%0, %1}, %2;" : "=f"(lo), "=f"(hi) : "l"(v));
}

// ---------------- scratch (device globals; allocation-free) ----------------
__device__ float g_yq[B_ * CK * N_];     // raw conv(q) (+bias)
__device__ float g_yk[B_ * CK * N_];     // raw conv(k) (+bias)
__device__ float g_yv[B_ * CV * N_];     // conv(v)
__device__ float g_WkT[CIN * CK];
__device__ float g_WvT[CIN * CV];
__device__ float g_scale[2 * CK];        // BN fused scale (q,k)
__device__ float g_shift[2 * CK];        // BN fused shift (q,k)
__device__ float g_spart[2 * 64 * 512];  // BN sum partials  [which*64+c][b*64+nblk]
__device__ float g_sspart[2 * 64 * 512]; // BN sumsq partials
__device__ float g_vpart[512 * 64];      // vsum partials [b*64+cv][nblk]
__device__ float g_vsum[B_ * CV];
__device__ float g_kvpart[KVCHUNKS * B_ * CK * CV];
__device__ float g_M[B_ * CK * CO];
__device__ float g_obias[B_ * CO];

// ---------------- K0: transpose weights ----------------
__global__ void prep_kernel(const float* __restrict__ Wk, const float* __restrict__ Wv) {
    int idx = blockIdx.x * 256 + threadIdx.x;   // 0 .. 16383
    int which = idx >> 13;
    int r = idx & 8191;
    int ci = r >> 6;
    int co = r & 63;
    float v = which ? Wv[co * CIN + ci] : Wk[co * CIN + ci];
    if (which) g_WvT[ci * 64 + co] = v;
    else       g_WkT[ci * 64 + co] = v;
}

// ---------------- K1: 1x1 conv + fused BN/vsum partials ----------------
// grid (64, B, 3), 256 threads. Tile 64co x 64n, thread tile 4x4, f32x2 packed.
__global__ __launch_bounds__(256) void conv_kernel(
    const float* __restrict__ xq, const float* __restrict__ xk,
    const float* __restrict__ xv,
    const float* __restrict__ bk, const float* __restrict__ bv)
{
    int which = blockIdx.z;
    const float* x    = (which == 0) ? xq : (which == 1) ? xk : xv;
    const float* WT   = (which == 2) ? g_WvT : g_WkT;
    const float* bias = (which == 2) ? bv : bk;
    float* y          = (which == 0) ? g_yq : (which == 1) ? g_yk : g_yv;

    int b  = blockIdx.y;
    int n0 = blockIdx.x * 64;
    int tid = threadIdx.x;
    int ty = tid >> 4, tx = tid & 15;

    __shared__ float Ws[64][64];   // [ci_k][co]
    __shared__ float Xs[64][64];   // [ci_k][n]

    u64 accp[2][4] = {};           // co-pairs (p) x n (i)

    for (int s = 0; s < 2; s++) {
        #pragma unroll
        for (int i = 0; i < 16; i++) {
            int idx = tid + i * 256;
            int cik = idx >> 6, nn = idx & 63;
            Xs[cik][nn] = x[((size_t)(b * CIN + s * 64 + cik)) * N_ + n0 + nn];
            Ws[cik][nn] = WT[(s * 64 + cik) * 64 + nn];
        }
        __syncthreads();
        #pragma unroll 16
        for (int ci = 0; ci < 64; ci++) {
            ulonglong2 a2 = *(const ulonglong2*)&Ws[ci][ty * 4];   // (co0,co1),(co2,co3)
            float4 q = *(const float4*)&Xs[ci][tx * 4];
            u64 q0 = bcast2(q.x), q1 = bcast2(q.y), q2 = bcast2(q.z), q3 = bcast2(q.w);
            fma2(accp[0][0], a2.x, q0); fma2(accp[1][0], a2.y, q0);
            fma2(accp[0][1], a2.x, q1); fma2(accp[1][1], a2.y, q1);
            fma2(accp[0][2], a2.x, q2); fma2(accp[1][2], a2.y, q2);
            fma2(accp[0][3], a2.x, q3); fma2(accp[1][3], a2.y, q3);
        }
        __syncthreads();
    }

    // unpack: yv[j][i] with co = ty*4+j, n = n0+tx*4+i
    float yvv[4][4];
    #pragma unroll
    for (int p = 0; p < 2; p++)
        #pragma unroll
        for (int i = 0; i < 4; i++) {
            float lo, hi; unpack2(lo, hi, accp[p][i]);
            yvv[2 * p][i] = lo; yvv[2 * p + 1][i] = hi;
        }

    float* red_s  = &Ws[0][0];   // reuse smem (post-sync)
    float* red_ss = &Xs[0][0];
    #pragma unroll
    for (int j = 0; j < 4; j++) {
        int co = ty * 4 + j;
        float bb = bias[co];
        float x0 = yvv[j][0] + bb, x1 = yvv[j][1] + bb;
        float x2 = yvv[j][2] + bb, x3 = yvv[j][3] + bb;
        float4 o = make_float4(x0, x1, x2, x3);
        *(float4*)&y[((size_t)(b * 64 + co)) * N_ + n0 + tx * 4] = o;
        red_s[co * 16 + tx]  = x0 + x1 + x2 + x3;
        red_ss[co * 16 + tx] = x0 * x0 + x1 * x1 + x2 * x2 + x3 * x3;
    }
    __syncthreads();
    if (tid < 64) {
        float S = 0.f, SS = 0.f;
        #pragma unroll
        for (int i = 0; i < 16; i++) { S += red_s[tid * 16 + i]; SS += red_ss[tid * 16 + i]; }
        if (which == 2) {
            g_vpart[(b * 64 + tid) * 64 + blockIdx.x] = S;
        } else {
            int o = which * 64 + tid;
            g_spart[o * 512 + b * 64 + blockIdx.x]  = S;
            g_sspart[o * 512 + b * 64 + blockIdx.x] = SS;
        }
    }
}

// ---------------- K2: reduce partials -> BN scale/shift, vsum ----------------
// grid 5, 128 threads (640 work items)
__global__ __launch_bounds__(128) void stats_reduce_kernel(
    const float* __restrict__ gamma, const float* __restrict__ beta)
{
    int gid = blockIdx.x * 128 + threadIdx.x;
    if (gid < 128) {
        int c = gid & 63;
        float S = 0.f, SS = 0.f;
        #pragma unroll 8
        for (int i = 0; i < 512; i++) {
            S  += g_spart[gid * 512 + i];
            SS += g_sspart[gid * 512 + i];
        }
        const float inv = 1.0f / 32768.0f;
        float mean = S * inv;
        float var  = SS * inv - mean * mean;
        float sc = gamma[c] * rsqrtf(var + 1e-5f);
        g_scale[gid] = sc;
        g_shift[gid] = beta[c] - mean * sc;
    } else if (gid < 640) {
        int t = gid - 128;      // b*64+cv
        float S = 0.f;
        #pragma unroll
        for (int i = 0; i < 64; i++) S += g_vpart[t * 64 + i];
        g_vsum[t] = S;
    }
}

// ---------------- K3: KV[b] = knorm[b] @ v[b]^T  (BN+L2norm fused in-tile) ---
// grid (KVCHUNKS, B), 256 threads
__global__ __launch_bounds__(256) void kv_kernel() {
    int chunk = blockIdx.x, b = blockIdx.y;
    __shared__ float Ks[64][65];
    __shared__ float Vs[64][65];
    __shared__ float scs[64], shs[64], ss4[4][64], rn[64];
    int tid = threadIdx.x;
    int ty = tid >> 4, tx = tid & 15;
    int n = tid & 63, cb = tid >> 6;

    if (tid < 64) { scs[tid] = g_scale[64 + tid]; shs[tid] = g_shift[64 + tid]; }
    __syncthreads();

    u64 accp[4][2] = {};

    for (int t = 0; t < 4; t++) {
        int n0 = chunk * 256 + t * 64;
        float tv[16]; float ssa = 0.f;
        #pragma unroll
        for (int i = 0; i < 16; i++) {
            int c = cb + i * 4;
            float raw = g_yk[((size_t)(b * 64 + c)) * N_ + n0 + n];
            float xv = raw * scs[c] + shs[c];
            tv[i] = xv; ssa += xv * xv;
            Vs[c][n] = g_yv[((size_t)(b * 64 + c)) * N_ + n0 + n];
        }
        ss4[cb][n] = ssa;
        __syncthreads();
        if (tid < 64)
            rn[tid] = 1.0f / (sqrtf(ss4[0][tid] + ss4[1][tid] + ss4[2][tid] + ss4[3][tid]) + 1e-7f);
        __syncthreads();
        float r = rn[n];
        #pragma unroll
        for (int i = 0; i < 16; i++) Ks[cb + i * 4][n] = tv[i] * r;
        __syncthreads();

        #pragma unroll 8
        for (int nn = 0; nn < 64; nn++) {
            float k0 = Ks[ty][nn], k1 = Ks[ty + 16][nn], k2 = Ks[ty + 32][nn], k3 = Ks[ty + 48][nn];
            float v0 = Vs[tx][nn], v1 = Vs[tx + 16][nn], v2 = Vs[tx + 32][nn], v3 = Vs[tx + 48][nn];
            u64 vp0 = pack2(v0, v1), vp1 = pack2(v2, v3);
            u64 kb0 = bcast2(k0), kb1 = bcast2(k1), kb2 = bcast2(k2), kb3 = bcast2(k3);
            fma2(accp[0][0], kb0, vp0); fma2(accp[0][1], kb0, vp1);
            fma2(accp[1][0], kb1, vp0); fma2(accp[1][1], kb1, vp1);
            fma2(accp[2][0], kb2, vp0); fma2(accp[2][1], kb2, vp1);
            fma2(accp[3][0], kb3, vp0); fma2(accp[3][1], kb3, vp1);
        }
        __syncthreads();
    }

    float* base = &g_kvpart[(((size_t)chunk * B_ + b)) * 4096];
    #pragma unroll
    for (int j = 0; j < 4; j++) {
        float lo0, hi0, lo1, hi1;
        unpack2(lo0, hi0, accp[j][0]);
        unpack2(lo1, hi1, accp[j][1]);
        float* rp = base + (size_t)(ty + j * 16) * 64;
        rp[tx]      = lo0;  rp[tx + 16] = hi0;
        rp[tx + 32] = lo1;  rp[tx + 48] = hi1;
    }
}

// ---------------- K4: per-batch M = KV @ Ww^T, obias = vsum@Ww^T + bw --------
__global__ __launch_bounds__(256) void m_kernel(
    const float* __restrict__ Ww, const float* __restrict__ bw)
{
    int b = blockIdx.x;
    __shared__ float KVs[64][64];   // 16 KB
    __shared__ float WwT[64][128];  // 32 KB
    int tid = threadIdx.x;

    for (int e = tid; e < 4096; e += 256) {
        float s = 0.f;
        #pragma unroll
        for (int c2 = 0; c2 < KVCHUNKS; c2++)
            s += g_kvpart[((size_t)c2 * B_ + b) * 4096 + e];
        KVs[e >> 6][e & 63] = s;
    }
    for (int e = tid; e < 8192; e += 256) {
        int cv = e >> 7, co = e & 127;
        WwT[cv][co] = Ww[co * CV + cv];
    }
    __syncthreads();

    int co = tid & 127;
    for (int ck = (tid >> 7); ck < 64; ck += 2) {
        float s = 0.f;
        #pragma unroll 8
        for (int cv = 0; cv < 64; cv++) s += KVs[ck][cv] * WwT[cv][co];
        g_M[((size_t)b * 64 + ck) * CO + co] = s;
    }
    if (tid < 128) {
        float s = bw[tid];
        #pragma unroll 8
        for (int cv = 0; cv < 64; cv++) s += g_vsum[b * 64 + cv] * WwT[cv][tid];
        g_obias[b * CO + tid] = s;
    }
}

// ---------------- K5: out = qnorm^T @ M + obias (BN+L2norm fused in-tile) ----
// grid (64, B, 2 co-halves), 256 threads. Tile 64co x 64n, 4x4 packed.
__global__ __launch_bounds__(256) void out_kernel(float* __restrict__ out) {
    int b = blockIdx.y, n0 = blockIdx.x * 64, ch = blockIdx.z;
    int tid = threadIdx.x;
    int ty = tid >> 4, tx = tid & 15;
    int n = tid & 63, cb = tid >> 6;

    __shared__ float Ms[64][64];   // [ck][co_local]
    __shared__ float Qs[64][64];   // [ck][n]
    __shared__ float scs[64], shs[64], ss4[4][64], rn[64];

    if (tid < 64) { scs[tid] = g_scale[tid]; shs[tid] = g_shift[tid]; }

    for (int e = tid; e < 4096; e += 256)
        Ms[e >> 6][e & 63] = g_M[((size_t)(b * 64 + (e >> 6))) * CO + ch * 64 + (e & 63)];

    __syncthreads();   // scs/shs visible

    float tv[16]; float ssa = 0.f;
    #pragma unroll
    for (int i = 0; i < 16; i++) {
        int c = cb + i * 4;
        float raw = g_yq[((size_t)(b * 64 + c)) * N_ + n0 + n];
        float xv = raw * scs[c] + shs[c];
        tv[i] = xv; ssa += xv * xv;
    }
    ss4[cb][n] = ssa;
    __syncthreads();
    if (tid < 64)
        rn[tid] = 1.0f / (sqrtf(ss4[0][tid] + ss4[1][tid] + ss4[2][tid] + ss4[3][tid]) + 1e-7f);
    __syncthreads();
    float r = rn[n];
    #pragma unroll
    for (int i = 0; i < 16; i++) Qs[cb + i * 4][n] = tv[i] * r;
    __syncthreads();

    u64 accp[2][4] = {};
    #pragma unroll 16
    for (int ck = 0; ck < 64; ck++) {
        ulonglong2 a2 = *(const ulonglong2*)&Ms[ck][ty * 4];
        float4 q = *(const float4*)&Qs[ck][tx * 4];
        u64 q0 = bcast2(q.x), q1 = bcast2(q.y), q2 = bcast2(q.z), q3 = bcast2(q.w);
        fma2(accp[0][0], a2.x, q0); fma2(accp[1][0], a2.y, q0);
        fma2(accp[0][1], a2.x, q1); fma2(accp[1][1], a2.y, q1);
        fma2(accp[0][2], a2.x, q2); fma2(accp[1][2], a2.y, q2);
        fma2(accp[0][3], a2.x, q3); fma2(accp[1][3], a2.y, q3);
    }

    float yvv[4][4];
    #pragma unroll
    for (int p = 0; p < 2; p++)
        #pragma unroll
        for (int i = 0; i < 4; i++) {
            float lo, hi; unpack2(lo, hi, accp[p][i]);
            yvv[2 * p][i] = lo; yvv[2 * p + 1][i] = hi;
        }
    #pragma unroll
    for (int j = 0; j < 4; j++) {
        int co = ch * 64 + ty * 4 + j;
        float ob = g_obias[b * CO + co];
        float4 o = make_float4(yvv[j][0] + ob, yvv[j][1] + ob, yvv[j][2] + ob, yvv[j][3] + ob);
        *(float4*)&out[((size_t)(b * CO + co)) * N_ + n0 + tx * 4] = o;
    }
}

// ---------------- launch ----------------
extern "C" void kernel_launch(void* const* d_in, const int* in_sizes, int n_in,
                              void* d_out, int out_size) {
    const float* q     = (const float*)d_in[0];
    const float* k     = (const float*)d_in[1];
    const float* v     = (const float*)d_in[2];
    const float* Wk    = (const float*)d_in[3];
    const float* bk    = (const float*)d_in[4];
    const float* gamma = (const float*)d_in[5];
    const float* beta  = (const float*)d_in[6];
    const float* Wv    = (const float*)d_in[7];
    const float* bv    = (const float*)d_in[8];
    const float* Ww    = (const float*)d_in[9];
    const float* bw    = (const float*)d_in[10];
    float* out = (float*)d_out;

    prep_kernel<<<64, 256>>>(Wk, Wv);
    conv_kernel<<<dim3(64, B_, 3), 256>>>(q, k, v, bk, bv);
    stats_reduce_kernel<<<5, 128>>>(gamma, beta);
    kv_kernel<<<dim3(KVCHUNKS, B_), 256>>>();
    m_kernel<<<B_, 256>>>(Ww, bw);
    out_kernel<<<dim3(64, B_, 2), 256>>>(out);
}

// round 4
// speedup vs baseline: 1.1571x; 1.1571x over previous
#include <cuda_runtime.h>
#include <math.h>

#define B_   8
#define CIN  128
#define CK   64
#define CV   64
#define CO   128
#define N_   4096
#define KVCHUNKS 32

typedef unsigned long long u64;

// ---------------- f32x2 packed-FMA helpers ----------------
__device__ __forceinline__ void fma2(u64 &d, u64 a, u64 b) {
    asm("fma.rn.f32x2 %0, %1, %2, %0;" : "+l"(d) : "l"(a), "l"(b));
}
__device__ __forceinline__ u64 bcast2(float x) {
    u64 r; asm("mov.b64 %0, {%1, %1};" : "=l"(r) : "f"(x)); return r;
}
__device__ __forceinline__ void unpack2(float &lo, float &hi, u64 v) {
    asm("mov.b64 {%0, %1}, %2;" : "=f"(lo), "=f"(hi) : "l"(v));
}

// ---------------- scratch ----------------
__device__ float g_yq[B_ * CK * N_];
__device__ float g_yk[B_ * CK * N_];
__device__ float g_yv[B_ * CV * N_];
__device__ float g_WkT[CIN * CK];
__device__ float g_WvT[CIN * CV];
__device__ float g_scale[2 * CK];
__device__ float g_shift[2 * CK];
__device__ float g_spart[2 * 64 * 256];   // [which*64+c][b*32+nblk]
__device__ float g_sspart[2 * 64 * 256];
__device__ float g_vpart[512 * 32];       // [b*64+cv][nblk]
__device__ float g_vsum[B_ * CV];
__device__ float g_kvpart[KVCHUNKS * B_ * CK * CV];
__device__ float g_M[B_ * CK * CO];
__device__ float g_obias[B_ * CO];

// ---------------- K0: transpose weights ----------------
__global__ void prep_kernel(const float* __restrict__ Wk, const float* __restrict__ Wv) {
    int idx = blockIdx.x * 256 + threadIdx.x;
    int which = idx >> 13;
    int r = idx & 8191;
    int ci = r >> 6, co = r & 63;
    float v = which ? Wv[co * CIN + ci] : Wk[co * CIN + ci];
    if (which) g_WvT[ci * 64 + co] = v;
    else       g_WkT[ci * 64 + co] = v;
}

// ---------------- K1: 1x1 conv, 64co x 128n tile, 8x4/thread, FFMA2 ---------
// grid (32, B_), 256 threads. which: 0=q, 1=k, 2=v. Fused BN/vsum partials.
// NOTE: output buffer selected IN-KERNEL (device symbols are not valid as
// host-side kernel args).
__global__ __launch_bounds__(256) void conv_kernel(
    const float* __restrict__ x, const float* __restrict__ bias, int which)
{
    const float* WT = (which == 2) ? g_WvT : g_WkT;
    float* y = (which == 0) ? g_yq : (which == 1) ? g_yk : g_yv;

    int b  = blockIdx.y;
    int n0 = blockIdx.x * 128;
    int tid = threadIdx.x;
    int cg = tid >> 5;          // co group 0..7 -> co0 = cg*8
    int tx = tid & 31;          // n group -> n_local = tx*4
    int co0 = cg * 8;

    __shared__ float Ws[64 * 64];    // [ci][co]   16KB
    __shared__ float Xs[64 * 128];   // [ci][n]    32KB

    u64 accp[4][4] = {};   // 4 co-pairs x 4 n

    for (int s = 0; s < 2; s++) {
        #pragma unroll
        for (int i = 0; i < 4; i++) {
            int e = tid + i * 256;                 // float4 index
            int row = e >> 4, col = (e & 15) * 4;
            *(float4*)&Ws[row * 64 + col] =
                *(const float4*)&WT[(s * 64 + row) * 64 + col];
        }
        #pragma unroll
        for (int i = 0; i < 8; i++) {
            int e = tid + i * 256;
            int row = e >> 5, col = (e & 31) * 4;
            *(float4*)&Xs[row * 128 + col] =
                *(const float4*)&x[((size_t)(b * CIN + s * 64 + row)) * N_ + n0 + col];
        }
        __syncthreads();
        #pragma unroll 16
        for (int ci = 0; ci < 64; ci++) {
            ulonglong2 w01 = *(const ulonglong2*)&Ws[ci * 64 + co0];      // co pairs 0,1
            ulonglong2 w23 = *(const ulonglong2*)&Ws[ci * 64 + co0 + 4];  // co pairs 2,3
            float4 q = *(const float4*)&Xs[ci * 128 + tx * 4];
            u64 q0 = bcast2(q.x), q1 = bcast2(q.y), q2 = bcast2(q.z), q3 = bcast2(q.w);
            fma2(accp[0][0], w01.x, q0); fma2(accp[1][0], w01.y, q0);
            fma2(accp[2][0], w23.x, q0); fma2(accp[3][0], w23.y, q0);
            fma2(accp[0][1], w01.x, q1); fma2(accp[1][1], w01.y, q1);
            fma2(accp[2][1], w23.x, q1); fma2(accp[3][1], w23.y, q1);
            fma2(accp[0][2], w01.x, q2); fma2(accp[1][2], w01.y, q2);
            fma2(accp[2][2], w23.x, q2); fma2(accp[3][2], w23.y, q2);
            fma2(accp[0][3], w01.x, q3); fma2(accp[1][3], w01.y, q3);
            fma2(accp[2][3], w23.x, q3); fma2(accp[3][3], w23.y, q3);
        }
        __syncthreads();
    }

    // unpack to 8 co x 4 n, add bias, store, accumulate partial stats
    float* red_s  = Ws;
    float* red_ss = Xs;

    float psum[8], psq[8];
    #pragma unroll
    for (int p = 0; p < 4; p++) {
        float lo[4], hi[4];
        #pragma unroll
        for (int i = 0; i < 4; i++) unpack2(lo[i], hi[i], accp[p][i]);
        int coA = co0 + 2 * p, coB = coA + 1;
        float bA = bias[coA], bB = bias[coB];
        float a0 = lo[0] + bA, a1 = lo[1] + bA, a2 = lo[2] + bA, a3 = lo[3] + bA;
        float c0 = hi[0] + bB, c1 = hi[1] + bB, c2 = hi[2] + bB, c3 = hi[3] + bB;
        *(float4*)&y[((size_t)(b * 64 + coA)) * N_ + n0 + tx * 4] = make_float4(a0, a1, a2, a3);
        *(float4*)&y[((size_t)(b * 64 + coB)) * N_ + n0 + tx * 4] = make_float4(c0, c1, c2, c3);
        psum[2 * p]     = a0 + a1 + a2 + a3;
        psq[2 * p]      = a0 * a0 + a1 * a1 + a2 * a2 + a3 * a3;
        psum[2 * p + 1] = c0 + c1 + c2 + c3;
        psq[2 * p + 1]  = c0 * c0 + c1 * c1 + c2 * c2 + c3 * c3;
    }
    #pragma unroll
    for (int j = 0; j < 8; j++) {
        int co = co0 + j;
        red_s[co * 33 + tx]  = psum[j];
        red_ss[co * 33 + tx] = psq[j];
    }
    __syncthreads();
    if (tid < 64) {
        float S = 0.f, SS = 0.f;
        #pragma unroll
        for (int i = 0; i < 32; i++) { S += red_s[tid * 33 + i]; SS += red_ss[tid * 33 + i]; }
        if (which == 2) {
            g_vpart[(b * 64 + tid) * 32 + blockIdx.x] = S;
        } else {
            int o = which * 64 + tid;
            g_spart[o * 256 + b * 32 + blockIdx.x]  = S;
            g_sspart[o * 256 + b * 32 + blockIdx.x] = SS;
        }
    }
}

// ---------------- K2: reduce partials -> BN scale/shift, vsum ----------------
__global__ __launch_bounds__(128) void stats_reduce_kernel(
    const float* __restrict__ gamma, const float* __restrict__ beta)
{
    int gid = blockIdx.x * 128 + threadIdx.x;
    if (gid < 128) {
        int c = gid & 63;
        float S = 0.f, SS = 0.f;
        #pragma unroll 8
        for (int i = 0; i < 256; i++) {
            S  += g_spart[gid * 256 + i];
            SS += g_sspart[gid * 256 + i];
        }
        const float inv = 1.0f / 32768.0f;
        float mean = S * inv;
        float var  = SS * inv - mean * mean;
        float sc = gamma[c] * rsqrtf(var + 1e-5f);
        g_scale[gid] = sc;
        g_shift[gid] = beta[c] - mean * sc;
    } else if (gid < 640) {
        int t = gid - 128;
        float S = 0.f;
        #pragma unroll
        for (int i = 0; i < 32; i++) S += g_vpart[t * 32 + i];
        g_vsum[t] = S;
    }
}

// ---------------- K3: apply BN + L2-normalize per column (in place) ----------
__global__ __launch_bounds__(128) void norm_kernel() {
    int which = blockIdx.y;
    float* y = which ? g_yk : g_yq;
    int tid = threadIdx.x;
    __shared__ float sc_s[64], sh_s[64];
    if (tid < 64) {
        sc_s[tid] = g_scale[which * 64 + tid];
        sh_s[tid] = g_shift[which * 64 + tid];
    }
    __syncthreads();
    int col = blockIdx.x * 128 + tid;
    int b = col >> 12, n = col & (N_ - 1);
    float v[64];
    float ss = 0.f;
    #pragma unroll
    for (int c = 0; c < 64; c++) {
        float t = y[((size_t)(b * 64 + c)) * N_ + n] * sc_s[c] + sh_s[c];
        v[c] = t; ss += t * t;
    }
    float rn = 1.0f / (sqrtf(ss) + 1e-7f);
    #pragma unroll
    for (int c = 0; c < 64; c++)
        y[((size_t)(b * 64 + c)) * N_ + n] = v[c] * rn;
}

// ---------------- K4: KV partials ------------------
__global__ __launch_bounds__(256) void kv_kernel() {
    int chunk = blockIdx.x, b = blockIdx.y;
    __shared__ float Ks[64][65];
    __shared__ float Vs[64][65];
    int tid = threadIdx.x;
    int ty = tid >> 4, tx = tid & 15;
    float acc[4][4] = {};

    for (int t = 0; t < 2; t++) {
        int n0 = chunk * 128 + t * 64;
        #pragma unroll
        for (int i = 0; i < 16; i++) {
            int idx = tid + i * 256;
            int c = idx >> 6, nn = idx & 63;
            Ks[c][nn] = g_yk[((size_t)(b * 64 + c)) * N_ + n0 + nn];
            Vs[c][nn] = g_yv[((size_t)(b * 64 + c)) * N_ + n0 + nn];
        }
        __syncthreads();
        #pragma unroll 8
        for (int n = 0; n < 64; n++) {
            float kv[4], vv[4];
            #pragma unroll
            for (int j = 0; j < 4; j++) kv[j] = Ks[ty + j * 16][n];
            #pragma unroll
            for (int j = 0; j < 4; j++) vv[j] = Vs[tx + j * 16][n];
            #pragma unroll
            for (int j = 0; j < 4; j++)
                #pragma unroll
                for (int i = 0; i < 4; i++)
                    acc[j][i] += kv[j] * vv[i];
        }
        __syncthreads();
    }
    #pragma unroll
    for (int j = 0; j < 4; j++)
        #pragma unroll
        for (int i = 0; i < 4; i++)
            g_kvpart[(((size_t)chunk * B_ + b) * 64 + ty + j * 16) * 64 + tx + i * 16] = acc[j][i];
}

// ---------------- K5: per-batch M = KV @ Ww^T, obias = vsum@Ww^T + bw --------
__global__ __launch_bounds__(256) void m_kernel(
    const float* __restrict__ Ww, const float* __restrict__ bw)
{
    int b = blockIdx.x;
    __shared__ float KVs[64][64];
    __shared__ float WwT[64][128];
    int tid = threadIdx.x;

    for (int e = tid; e < 4096; e += 256) {
        float s = 0.f;
        #pragma unroll
        for (int c2 = 0; c2 < KVCHUNKS; c2++)
            s += g_kvpart[((size_t)c2 * B_ + b) * 4096 + e];
        KVs[e >> 6][e & 63] = s;
    }
    for (int e = tid; e < 8192; e += 256) {
        int cv = e >> 7, co = e & 127;
        WwT[cv][co] = Ww[co * CV + cv];
    }
    __syncthreads();

    int co = tid & 127;
    for (int ck = (tid >> 7); ck < 64; ck += 2) {
        float s = 0.f;
        #pragma unroll 8
        for (int cv = 0; cv < 64; cv++) s += KVs[ck][cv] * WwT[cv][co];
        g_M[((size_t)b * 64 + ck) * CO + co] = s;
    }
    if (tid < 128) {
        float s = bw[tid];
        #pragma unroll 8
        for (int cv = 0; cv < 64; cv++) s += g_vsum[b * 64 + cv] * WwT[cv][tid];
        g_obias[b * CO + tid] = s;
    }
}

// ---------------- K6: out = qnorm^T @ M + obias ---------------
__global__ __launch_bounds__(256) void out_kernel(float* __restrict__ out) {
    int b = blockIdx.y, n0 = blockIdx.x * 64;
    int tid = threadIdx.x;
    int ty = tid >> 4, tx = tid & 15;
    __shared__ float Ms[64][128];
    __shared__ float Qs[64][64];

    for (int e = tid; e < 8192; e += 256)
        Ms[e >> 7][e & 127] = g_M[(size_t)b * 8192 + e];
    for (int e = tid; e < 4096; e += 256)
        Qs[e >> 6][e & 63] = g_yq[((size_t)(b * 64 + (e >> 6))) * N_ + n0 + (e & 63)];
    __syncthreads();

    float acc[8][4] = {};
    #pragma unroll 8
    for (int ck = 0; ck < 64; ck++) {
        float4 a0 = *(const float4*)&Ms[ck][ty * 8];
        float4 a1 = *(const float4*)&Ms[ck][ty * 8 + 4];
        float4 q  = *(const float4*)&Qs[ck][tx * 4];
        acc[0][0] += a0.x * q.x; acc[0][1] += a0.x * q.y; acc[0][2] += a0.x * q.z; acc[0][3] += a0.x * q.w;
        acc[1][0] += a0.y * q.x; acc[1][1] += a0.y * q.y; acc[1][2] += a0.y * q.z; acc[1][3] += a0.y * q.w;
        acc[2][0] += a0.z * q.x; acc[2][1] += a0.z * q.y; acc[2][2] += a0.z * q.z; acc[2][3] += a0.z * q.w;
        acc[3][0] += a0.w * q.x; acc[3][1] += a0.w * q.y; acc[3][2] += a0.w * q.z; acc[3][3] += a0.w * q.w;
        acc[4][0] += a1.x * q.x; acc[4][1] += a1.x * q.y; acc[4][2] += a1.x * q.z; acc[4][3] += a1.x * q.w;
        acc[5][0] += a1.y * q.x; acc[5][1] += a1.y * q.y; acc[5][2] += a1.y * q.z; acc[5][3] += a1.y * q.w;
        acc[6][0] += a1.z * q.x; acc[6][1] += a1.z * q.y; acc[6][2] += a1.z * q.z; acc[6][3] += a1.z * q.w;
        acc[7][0] += a1.w * q.x; acc[7][1] += a1.w * q.y; acc[7][2] += a1.w * q.z; acc[7][3] += a1.w * q.w;
    }
    #pragma unroll
    for (int j = 0; j < 8; j++) {
        int co = ty * 8 + j;
        float ob = g_obias[b * CO + co];
        float4 o = make_float4(acc[j][0] + ob, acc[j][1] + ob, acc[j][2] + ob, acc[j][3] + ob);
        *(float4*)&out[((size_t)(b * CO + co)) * N_ + n0 + tx * 4] = o;
    }
}

// ---------------- launch ----------------
extern "C" void kernel_launch(void* const* d_in, const int* in_sizes, int n_in,
                              void* d_out, int out_size) {
    const float* q     = (const float*)d_in[0];
    const float* k     = (const float*)d_in[1];
    const float* v     = (const float*)d_in[2];
    const float* Wk    = (const float*)d_in[3];
    const float* bk    = (const float*)d_in[4];
    const float* gamma = (const float*)d_in[5];
    const float* beta  = (const float*)d_in[6];
    const float* Wv    = (const float*)d_in[7];
    const float* bv    = (const float*)d_in[8];
    const float* Ww    = (const float*)d_in[9];
    const float* bw    = (const float*)d_in[10];
    float* out = (float*)d_out;

    prep_kernel<<<64, 256>>>(Wk, Wv);
    conv_kernel<<<dim3(32, B_), 256>>>(q, bk, 0);
    conv_kernel<<<dim3(32, B_), 256>>>(k, bk, 1);
    conv_kernel<<<dim3(32, B_), 256>>>(v, bv, 2);
    stats_reduce_kernel<<<5, 128>>>(gamma, beta);
    norm_kernel<<<dim3(256, 2), 128>>>();
    kv_kernel<<<dim3(KVCHUNKS, B_), 256>>>();
    m_kernel<<<B_, 256>>>(Ww, bw);
    out_kernel<<<dim3(64, B_), 256>>>(out);
}

// round 5
// speedup vs baseline: 1.2294x; 1.0625x over previous
#include <cuda_runtime.h>
#include <math.h>

#define B_   8
#define CIN  128
#define CK   64
#define CV   64
#define CO   128
#define N_   4096
#define KVCHUNKS 32

typedef unsigned long long u64;

// ---------------- f32x2 packed-FMA helpers ----------------
__device__ __forceinline__ void fma2(u64 &d, u64 a, u64 b) {
    asm("fma.rn.f32x2 %0, %1, %2, %0;" : "+l"(d) : "l"(a), "l"(b));
}
__device__ __forceinline__ u64 bcast2(float x) {
    u64 r; asm("mov.b64 %0, {%1, %1};" : "=l"(r) : "f"(x)); return r;
}
__device__ __forceinline__ void unpack2(float &lo, float &hi, u64 v) {
    asm("mov.b64 {%0, %1}, %2;" : "=f"(lo), "=f"(hi) : "l"(v));
}

// ---------------- scratch ----------------
__device__ float g_yq[B_ * CK * N_];
__device__ float g_yk[B_ * CK * N_];
__device__ float g_yv[B_ * CV * N_];
__device__ float g_WkT[CIN * CK];
__device__ float g_WvT[CIN * CV];
__device__ float g_scale[2 * CK];
__device__ float g_shift[2 * CK];
__device__ float g_spart[2 * 64 * 256];   // [which*64+c][b*32+nblk]
__device__ float g_sspart[2 * 64 * 256];
__device__ float g_vpart[512 * 32];       // [b*64+cv][nblk]
__device__ float g_vsum[B_ * CV];
__device__ float g_kvpart[KVCHUNKS * B_ * CK * CV];
__device__ float g_M[B_ * CK * CO];
__device__ float g_obias[B_ * CO];

// ---------------- K0: transpose weights ----------------
__global__ void prep_kernel(const float* __restrict__ Wk, const float* __restrict__ Wv) {
    int idx = blockIdx.x * 256 + threadIdx.x;
    int which = idx >> 13;
    int r = idx & 8191;
    int ci = r >> 6, co = r & 63;
    float v = which ? Wv[co * CIN + ci] : Wk[co * CIN + ci];
    if (which) g_WvT[ci * 64 + co] = v;
    else       g_WkT[ci * 64 + co] = v;
}

// ---------------- K1: 1x1 conv, 64co x 128n tile, 8x4/thread, FFMA2 ---------
// grid (32, B_, 3), 256 threads. z: 0=q, 1=k, 2=v. Fused BN/vsum partials.
__global__ __launch_bounds__(256) void conv_kernel(
    const float* __restrict__ xq, const float* __restrict__ xk,
    const float* __restrict__ xv,
    const float* __restrict__ bk, const float* __restrict__ bv)
{
    int which = blockIdx.z;
    const float* x    = (which == 0) ? xq : (which == 1) ? xk : xv;
    const float* WT   = (which == 2) ? g_WvT : g_WkT;
    const float* bias = (which == 2) ? bv : bk;
    float* y          = (which == 0) ? g_yq : (which == 1) ? g_yk : g_yv;

    int b  = blockIdx.y;
    int n0 = blockIdx.x * 128;
    int tid = threadIdx.x;
    int cg = tid >> 5;          // co group 0..7 -> co0 = cg*8
    int tx = tid & 31;          // n group -> n_local = tx*4
    int co0 = cg * 8;

    __shared__ float Ws[64 * 64];    // [ci][co]   16KB
    __shared__ float Xs[64 * 128];   // [ci][n]    32KB

    u64 accp[4][4] = {};   // 4 co-pairs x 4 n

    for (int s = 0; s < 2; s++) {
        #pragma unroll
        for (int i = 0; i < 4; i++) {
            int e = tid + i * 256;                 // float4 index
            int row = e >> 4, col = (e & 15) * 4;
            *(float4*)&Ws[row * 64 + col] =
                *(const float4*)&WT[(s * 64 + row) * 64 + col];
        }
        #pragma unroll
        for (int i = 0; i < 8; i++) {
            int e = tid + i * 256;
            int row = e >> 5, col = (e & 31) * 4;
            *(float4*)&Xs[row * 128 + col] =
                *(const float4*)&x[((size_t)(b * CIN + s * 64 + row)) * N_ + n0 + col];
        }
        __syncthreads();
        #pragma unroll 16
        for (int ci = 0; ci < 64; ci++) {
            ulonglong2 w01 = *(const ulonglong2*)&Ws[ci * 64 + co0];
            ulonglong2 w23 = *(const ulonglong2*)&Ws[ci * 64 + co0 + 4];
            float4 q = *(const float4*)&Xs[ci * 128 + tx * 4];
            u64 q0 = bcast2(q.x), q1 = bcast2(q.y), q2 = bcast2(q.z), q3 = bcast2(q.w);
            fma2(accp[0][0], w01.x, q0); fma2(accp[1][0], w01.y, q0);
            fma2(accp[2][0], w23.x, q0); fma2(accp[3][0], w23.y, q0);
            fma2(accp[0][1], w01.x, q1); fma2(accp[1][1], w01.y, q1);
            fma2(accp[2][1], w23.x, q1); fma2(accp[3][1], w23.y, q1);
            fma2(accp[0][2], w01.x, q2); fma2(accp[1][2], w01.y, q2);
            fma2(accp[2][2], w23.x, q2); fma2(accp[3][2], w23.y, q2);
            fma2(accp[0][3], w01.x, q3); fma2(accp[1][3], w01.y, q3);
            fma2(accp[2][3], w23.x, q3); fma2(accp[3][3], w23.y, q3);
        }
        __syncthreads();
    }

    float* red_s  = Ws;
    float* red_ss = Xs;

    float psum[8], psq[8];
    #pragma unroll
    for (int p = 0; p < 4; p++) {
        float lo[4], hi[4];
        #pragma unroll
        for (int i = 0; i < 4; i++) unpack2(lo[i], hi[i], accp[p][i]);
        int coA = co0 + 2 * p, coB = coA + 1;
        float bA = bias[coA], bB = bias[coB];
        float a0 = lo[0] + bA, a1 = lo[1] + bA, a2 = lo[2] + bA, a3 = lo[3] + bA;
        float c0 = hi[0] + bB, c1 = hi[1] + bB, c2 = hi[2] + bB, c3 = hi[3] + bB;
        *(float4*)&y[((size_t)(b * 64 + coA)) * N_ + n0 + tx * 4] = make_float4(a0, a1, a2, a3);
        *(float4*)&y[((size_t)(b * 64 + coB)) * N_ + n0 + tx * 4] = make_float4(c0, c1, c2, c3);
        psum[2 * p]     = a0 + a1 + a2 + a3;
        psq[2 * p]      = a0 * a0 + a1 * a1 + a2 * a2 + a3 * a3;
        psum[2 * p + 1] = c0 + c1 + c2 + c3;
        psq[2 * p + 1]  = c0 * c0 + c1 * c1 + c2 * c2 + c3 * c3;
    }
    #pragma unroll
    for (int j = 0; j < 8; j++) {
        int co = co0 + j;
        red_s[co * 33 + tx]  = psum[j];
        red_ss[co * 33 + tx] = psq[j];
    }
    __syncthreads();
    if (tid < 64) {
        float S = 0.f, SS = 0.f;
        #pragma unroll
        for (int i = 0; i < 32; i++) { S += red_s[tid * 33 + i]; SS += red_ss[tid * 33 + i]; }
        if (which == 2) {
            g_vpart[(b * 64 + tid) * 32 + blockIdx.x] = S;
        } else {
            int o = which * 64 + tid;
            g_spart[o * 256 + b * 32 + blockIdx.x]  = S;
            g_sspart[o * 256 + b * 32 + blockIdx.x] = SS;
        }
    }
}

// ---------------- K2: reduce partials -> BN scale/shift, vsum ----------------
__global__ __launch_bounds__(128) void stats_reduce_kernel(
    const float* __restrict__ gamma, const float* __restrict__ beta)
{
    int gid = blockIdx.x * 128 + threadIdx.x;
    if (gid < 128) {
        int c = gid & 63;
        float S = 0.f, SS = 0.f;
        #pragma unroll 8
        for (int i = 0; i < 256; i++) {
            S  += g_spart[gid * 256 + i];
            SS += g_sspart[gid * 256 + i];
        }
        const float inv = 1.0f / 32768.0f;
        float mean = S * inv;
        float var  = SS * inv - mean * mean;
        float sc = gamma[c] * rsqrtf(var + 1e-5f);
        g_scale[gid] = sc;
        g_shift[gid] = beta[c] - mean * sc;
    } else if (gid < 640) {
        int t = gid - 128;
        float S = 0.f;
        #pragma unroll
        for (int i = 0; i < 32; i++) S += g_vpart[t * 32 + i];
        g_vsum[t] = S;
    }
}

// ---------------- K3: apply BN + L2-normalize per column (in place) ----------
__global__ __launch_bounds__(128) void norm_kernel() {
    int which = blockIdx.y;
    float* y = which ? g_yk : g_yq;
    int tid = threadIdx.x;
    __shared__ float sc_s[64], sh_s[64];
    if (tid < 64) {
        sc_s[tid] = g_scale[which * 64 + tid];
        sh_s[tid] = g_shift[which * 64 + tid];
    }
    __syncthreads();
    int col = blockIdx.x * 128 + tid;
    int b = col >> 12, n = col & (N_ - 1);
    float v[64];
    float ss = 0.f;
    #pragma unroll
    for (int c = 0; c < 64; c++) {
        float t = y[((size_t)(b * 64 + c)) * N_ + n] * sc_s[c] + sh_s[c];
        v[c] = t; ss += t * t;
    }
    float rn = 1.0f / (sqrtf(ss) + 1e-7f);
    #pragma unroll
    for (int c = 0; c < 64; c++)
        y[((size_t)(b * 64 + c)) * N_ + n] = v[c] * rn;
}

// ---------------- K4: KV partials ------------------
__global__ __launch_bounds__(256) void kv_kernel() {
    int chunk = blockIdx.x, b = blockIdx.y;
    __shared__ float Ks[64][65];
    __shared__ float Vs[64][65];
    int tid = threadIdx.x;
    int ty = tid >> 4, tx = tid & 15;
    float acc[4][4] = {};

    for (int t = 0; t < 2; t++) {
        int n0 = chunk * 128 + t * 64;
        #pragma unroll
        for (int i = 0; i < 16; i++) {
            int idx = tid + i * 256;
            int c = idx >> 6, nn = idx & 63;
            Ks[c][nn] = g_yk[((size_t)(b * 64 + c)) * N_ + n0 + nn];
            Vs[c][nn] = g_yv[((size_t)(b * 64 + c)) * N_ + n0 + nn];
        }
        __syncthreads();
        #pragma unroll 8
        for (int n = 0; n < 64; n++) {
            float kv[4], vv[4];
            #pragma unroll
            for (int j = 0; j < 4; j++) kv[j] = Ks[ty + j * 16][n];
            #pragma unroll
            for (int j = 0; j < 4; j++) vv[j] = Vs[tx + j * 16][n];
            #pragma unroll
            for (int j = 0; j < 4; j++)
                #pragma unroll
                for (int i = 0; i < 4; i++)
                    acc[j][i] += kv[j] * vv[i];
        }
        __syncthreads();
    }
    #pragma unroll
    for (int j = 0; j < 4; j++)
        #pragma unroll
        for (int i = 0; i < 4; i++)
            g_kvpart[(((size_t)chunk * B_ + b) * 64 + ty + j * 16) * 64 + tx + i * 16] = acc[j][i];
}

// ---------------- K5: per-batch M = KV @ Ww^T, obias = vsum@Ww^T + bw --------
__global__ __launch_bounds__(256) void m_kernel(
    const float* __restrict__ Ww, const float* __restrict__ bw)
{
    int b = blockIdx.x;
    __shared__ float KVs[64][64];
    __shared__ float WwT[64][128];
    int tid = threadIdx.x;

    for (int e = tid; e < 4096; e += 256) {
        float s = 0.f;
        #pragma unroll
        for (int c2 = 0; c2 < KVCHUNKS; c2++)
            s += g_kvpart[((size_t)c2 * B_ + b) * 4096 + e];
        KVs[e >> 6][e & 63] = s;
    }
    for (int e = tid; e < 8192; e += 256) {
        int cv = e >> 7, co = e & 127;
        WwT[cv][co] = Ww[co * CV + cv];
    }
    __syncthreads();

    int co = tid & 127;
    for (int ck = (tid >> 7); ck < 64; ck += 2) {
        float s = 0.f;
        #pragma unroll 8
        for (int cv = 0; cv < 64; cv++) s += KVs[ck][cv] * WwT[cv][co];
        g_M[((size_t)b * 64 + ck) * CO + co] = s;
    }
    if (tid < 128) {
        float s = bw[tid];
        #pragma unroll 8
        for (int cv = 0; cv < 64; cv++) s += g_vsum[b * 64 + cv] * WwT[cv][tid];
        g_obias[b * CO + tid] = s;
    }
}

// ---------------- K6: out = qnorm^T @ M + obias ---------------
__global__ __launch_bounds__(256) void out_kernel(float* __restrict__ out) {
    int b = blockIdx.y, n0 = blockIdx.x * 64;
    int tid = threadIdx.x;
    int ty = tid >> 4, tx = tid & 15;
    __shared__ float Ms[64][128];
    __shared__ float Qs[64][64];

    for (int e = tid; e < 8192; e += 256)
        Ms[e >> 7][e & 127] = g_M[(size_t)b * 8192 + e];
    for (int e = tid; e < 4096; e += 256)
        Qs[e >> 6][e & 63] = g_yq[((size_t)(b * 64 + (e >> 6))) * N_ + n0 + (e & 63)];
    __syncthreads();

    float acc[8][4] = {};
    #pragma unroll 8
    for (int ck = 0; ck < 64; ck++) {
        float4 a0 = *(const float4*)&Ms[ck][ty * 8];
        float4 a1 = *(const float4*)&Ms[ck][ty * 8 + 4];
        float4 q  = *(const float4*)&Qs[ck][tx * 4];
        acc[0][0] += a0.x * q.x; acc[0][1] += a0.x * q.y; acc[0][2] += a0.x * q.z; acc[0][3] += a0.x * q.w;
        acc[1][0] += a0.y * q.x; acc[1][1] += a0.y * q.y; acc[1][2] += a0.y * q.z; acc[1][3] += a0.y * q.w;
        acc[2][0] += a0.z * q.x; acc[2][1] += a0.z * q.y; acc[2][2] += a0.z * q.z; acc[2][3] += a0.z * q.w;
        acc[3][0] += a0.w * q.x; acc[3][1] += a0.w * q.y; acc[3][2] += a0.w * q.z; acc[3][3] += a0.w * q.w;
        acc[4][0] += a1.x * q.x; acc[4][1] += a1.x * q.y; acc[4][2] += a1.x * q.z; acc[4][3] += a1.x * q.w;
        acc[5][0] += a1.y * q.x; acc[5][1] += a1.y * q.y; acc[5][2] += a1.y * q.z; acc[5][3] += a1.y * q.w;
        acc[6][0] += a1.z * q.x; acc[6][1] += a1.z * q.y; acc[6][2] += a1.z * q.z; acc[6][3] += a1.z * q.w;
        acc[7][0] += a1.w * q.x; acc[7][1] += a1.w * q.y; acc[7][2] += a1.w * q.z; acc[7][3] += a1.w * q.w;
    }
    #pragma unroll
    for (int j = 0; j < 8; j++) {
        int co = ty * 8 + j;
        float ob = g_obias[b * CO + co];
        float4 o = make_float4(acc[j][0] + ob, acc[j][1] + ob, acc[j][2] + ob, acc[j][3] + ob);
        *(float4*)&out[((size_t)(b * CO + co)) * N_ + n0 + tx * 4] = o;
    }
}

// ---------------- launch ----------------
extern "C" void kernel_launch(void* const* d_in, const int* in_sizes, int n_in,
                              void* d_out, int out_size) {
    const float* q     = (const float*)d_in[0];
    const float* k     = (const float*)d_in[1];
    const float* v     = (const float*)d_in[2];
    const float* Wk    = (const float*)d_in[3];
    const float* bk    = (const float*)d_in[4];
    const float* gamma = (const float*)d_in[5];
    const float* beta  = (const float*)d_in[6];
    const float* Wv    = (const float*)d_in[7];
    const float* bv    = (const float*)d_in[8];
    const float* Ww    = (const float*)d_in[9];
    const float* bw    = (const float*)d_in[10];
    float* out = (float*)d_out;

    prep_kernel<<<64, 256>>>(Wk, Wv);
    conv_kernel<<<dim3(32, B_, 3), 256>>>(q, k, v, bk, bv);
    stats_reduce_kernel<<<5, 128>>>(gamma, beta);
    norm_kernel<<<dim3(256, 2), 128>>>();
    kv_kernel<<<dim3(KVCHUNKS, B_), 256>>>();
    m_kernel<<<B_, 256>>>(Ww, bw);
    out_kernel<<<dim3(64, B_), 256>>>(out);
}